// round 15
// baseline (speedup 1.0000x reference)
#include <cuda_runtime.h>
#include <cuda_fp16.h>
#include <cstdint>

__device__ float g_y[8192*128], g_v[8192*128];
__device__ float4 g_wp0[8*16*32], g_wp1[4*16*32], g_wp2[8*16*32],
                  g_wp3[8*16*32], g_wp4[8*16*32];

#define INV32 0.03125f

__device__ __forceinline__ uint32_t pkbf(float lo, float hi) {
    uint32_t r; asm("cvt.rn.bf16x2.f32 %0, %1, %2;" : "=r"(r) : "f"(hi), "f"(lo)); return r;
}
__device__ __forceinline__ void bsplit(float x0, float x1, uint32_t& h, uint32_t& l) {
    h = pkbf(x0, x1);
    float r0 = x0 - __uint_as_float(h << 16);
    float r1 = x1 - __uint_as_float(h & 0xffff0000u);
    l = pkbf(r0, r1);
}
__device__ __forceinline__ uint32_t pkh(float x0, float x1) {
    __half2 hh = __floats2half2_rn(x0, x1);
    return *(uint32_t*)&hh;
}
__device__ __forceinline__ void hsplit(float x0, float x1, uint32_t& h, uint32_t& l) {
    __half2 hh = __floats2half2_rn(x0, x1);
    float2 bb = __half22float2(hh);
    h = *(uint32_t*)&hh;
    l = pkh(x0 - bb.x, x1 - bb.y);
}
__device__ __forceinline__ void mma16(float* c, const uint32_t* a, uint32_t b0, uint32_t b1) {
    asm volatile("mma.sync.aligned.m16n8k16.row.col.f32.bf16.bf16.f32 "
        "{%0,%1,%2,%3},{%4,%5,%6,%7},{%8,%9},{%0,%1,%2,%3};"
        : "+f"(c[0]), "+f"(c[1]), "+f"(c[2]), "+f"(c[3])
        : "r"(a[0]), "r"(a[1]), "r"(a[2]), "r"(a[3]), "r"(b0), "r"(b1));
}
__device__ __forceinline__ void mma16f(float* c, const uint32_t* a, uint32_t b0, uint32_t b1) {
    asm volatile("mma.sync.aligned.m16n8k16.row.col.f32.f16.f16.f32 "
        "{%0,%1,%2,%3},{%4,%5,%6,%7},{%8,%9},{%0,%1,%2,%3};"
        : "+f"(c[0]), "+f"(c[1]), "+f"(c[2]), "+f"(c[3])
        : "r"(a[0]), "r"(a[1]), "r"(a[2]), "r"(a[3]), "r"(b0), "r"(b1));
}
__device__ __forceinline__ float sspf(float x) {
    float e = __expf(-fabsf(x));
    return fmaxf(x, 0.f) + __logf(1.f + e) - 0.69314718055994531f;
}

// ---- bf16x3 pstep (validated; gemmB/gemmC) ----
template <int NB>
__device__ __forceinline__ void pstep(const uint2* Ap, int lda, int m0, int kc,
                                      const float4* Bs, int lane, float (*acc)[4]) {
    int g = lane >> 2, t = lane & 3;
    const uint2* p0 = Ap + (m0 + g) * lda + kc + t;
    const uint2* p1 = p0 + 8 * lda;
    uint2 a0 = p0[0], a1 = p1[0], a2 = p0[4], a3 = p1[4];
    uint32_t ah[4] = {a0.x, a1.x, a2.x, a3.x};
    uint32_t al[4] = {a0.y, a1.y, a2.y, a3.y};
    float4 b[NB];
#pragma unroll
    for (int j = 0; j < NB; ++j) b[j] = Bs[j * 32 + lane];
#pragma unroll
    for (int j = 0; j < NB; ++j)
        mma16(acc[j], ah, __float_as_uint(b[j].x), __float_as_uint(b[j].z));
#pragma unroll
    for (int j = 0; j < NB; ++j)
        mma16(acc[j], ah, __float_as_uint(b[j].y), __float_as_uint(b[j].w));
#pragma unroll
    for (int j = 0; j < NB; ++j)
        mma16(acc[j], al, __float_as_uint(b[j].x), __float_as_uint(b[j].z));
}

// ---- fp16x2 step, MT=2/NB=4: A plain fp16 pairs-interleaved, B fp16 hi/lo frags ----
__device__ __forceinline__ void psf(const uint32_t* Ap, int lda, int m0, int ks8,
                                    const float4* Bs, int lane, float acc[2][4][4]) {
    int g = lane >> 2, t = lane & 3;
    uint32_t a[2][4];
#pragma unroll
    for (int mt = 0; mt < 2; ++mt) {
        const uint32_t* pr = Ap + (m0 + mt * 16 + g) * lda + ks8 + 2 * t;
        uint2 v0 = *(const uint2*)pr;
        uint2 v1 = *(const uint2*)(pr + 8 * lda);
        a[mt][0] = v0.x; a[mt][1] = v1.x; a[mt][2] = v0.y; a[mt][3] = v1.y;
    }
    float4 b[4];
#pragma unroll
    for (int j = 0; j < 4; ++j) b[j] = Bs[j * 32 + lane];
#pragma unroll
    for (int j = 0; j < 4; ++j) {
        mma16f(acc[0][j], a[0], __float_as_uint(b[j].x), __float_as_uint(b[j].z));
        mma16f(acc[1][j], a[1], __float_as_uint(b[j].x), __float_as_uint(b[j].z));
    }
#pragma unroll
    for (int j = 0; j < 4; ++j) {
        mma16f(acc[0][j], a[0], __float_as_uint(b[j].y), __float_as_uint(b[j].w));
        mma16f(acc[1][j], a[1], __float_as_uint(b[j].y), __float_as_uint(b[j].w));
    }
}

// pack: W1/W2 -> fp16 hi/lo frags scaled x32; W0/W3/W4 -> bf16 hi/lo frags
__global__ void pack5(const float* w0, const float* w1, const float* w2,
                      const float* w3, const float* w4,
                      float4* o0, float4* o1, float4* o2, float4* o3, float4* o4) {
    int b = blockIdx.x, lane = threadIdx.x, kidx = b >> 4, nb = b & 15;
    const float* W; float4* D; int K, ks, fp = 0;
    if (kidx < 8)       { W = w0; D = o0; K = 128; ks = kidx;      }
    else if (kidx < 12) { W = w1; D = o1; K = 50;  ks = kidx - 8;  fp = 1; }
    else if (kidx < 20) { W = w2; D = o2; K = 128; ks = kidx - 12; fp = 1; }
    else if (kidx < 28) { W = w3; D = o3; K = 128; ks = kidx - 20; }
    else                { W = w4; D = o4; K = 128; ks = kidx - 28; }
    int g = lane >> 2, t = lane & 3, n = nb * 8 + g, k0 = ks * 16 + 2 * t;
    float a = (k0 < K) ? W[n * K + k0] : 0.f, b1 = (k0 + 1 < K) ? W[n * K + k0 + 1] : 0.f;
    float c = (k0 + 8 < K) ? W[n * K + k0 + 8] : 0.f, d = (k0 + 9 < K) ? W[n * K + k0 + 9] : 0.f;
    uint32_t h0, l0, h1, l1;
    if (fp) { hsplit(a * 32.f, b1 * 32.f, h0, l0); hsplit(c * 32.f, d * 32.f, h1, l1); }
    else    { bsplit(a, b1, h0, l0); bsplit(c, d, h1, l1); }
    D[(ks * 16 + nb) * 32 + lane] = make_float4(__uint_as_float(h0), __uint_as_float(l0),
                                                __uint_as_float(h1), __uint_as_float(l1));
}

__global__ void zerov(float4* p) {
    p[(size_t)blockIdx.x * 512 + threadIdx.x] = make_float4(0.f, 0.f, 0.f, 0.f);
}

__global__ __launch_bounds__(512, 1)
void gemmB(const float* __restrict__ A, const float4* __restrict__ Bp,
           float* __restrict__ out) {
    extern __shared__ __align__(16) float sm[];
    float4* bf = (float4*)sm;
    uint2*  ap = (uint2*)(sm + 16384);
    int tid = threadIdx.x, lane = tid & 31, warp = tid >> 5;
    int wm = warp & 3, wn = warp >> 2, g = lane >> 2, t = lane & 3;
    int row0 = blockIdx.x * 64;
    for (int i = tid; i < 4096; i += 512) bf[i] = Bp[i];
    for (int i = tid; i < 4096; i += 512) {
        int r = i >> 6, cp = i & 63;
        float2 v = *(const float2*)(A + (size_t)(row0 + r) * 128 + 2 * cp);
        uint32_t h, l; bsplit(v.x, v.y, h, l);
        ap[r * 68 + cp] = make_uint2(h, l);
    }
    __syncthreads();
    float acc[4][4]{};
#pragma unroll
    for (int ks = 0; ks < 8; ++ks)
        pstep<4>(ap, 68, wm * 16, ks * 8, bf + (ks * 16 + wn * 4) * 32, lane, acc);
    int r0 = row0 + wm * 16 + g, r1 = r0 + 8;
#pragma unroll
    for (int j = 0; j < 4; ++j) {
        int c = wn * 32 + j * 8 + 2 * t;
        *(float2*)(out + (size_t)r0 * 128 + c) = make_float2(acc[j][0], acc[j][1]);
        *(float2*)(out + (size_t)r1 * 128 + c) = make_float2(acc[j][2], acc[j][3]);
    }
}

__global__ __launch_bounds__(512, 1)
void gemmC(const float* __restrict__ A, const float4* __restrict__ B3,
           const float4* __restrict__ B4, const float* __restrict__ b3,
           const float* __restrict__ b4, float* __restrict__ out) {
    extern __shared__ __align__(16) float sm[];
    float4* f3 = (float4*)sm;
    float4* f4 = (float4*)(sm + 16384);
    uint2*  ap = (uint2*)(sm + 32768);
    uint2*  vp = (uint2*)(sm + 41472);
    float* b3s = sm + 50176; float* b4s = sm + 50304;
    int tid = threadIdx.x, lane = tid & 31, warp = tid >> 5;
    int wm = warp & 3, wn = warp >> 2, g = lane >> 2, t = lane & 3;
    int row0 = blockIdx.x * 64;
    for (int i = tid; i < 4096; i += 512) { f3[i] = B3[i]; f4[i] = B4[i]; }
    if (tid < 128) { b3s[tid] = b3[tid]; b4s[tid] = b4[tid]; }
    for (int i = tid; i < 4096; i += 512) {
        int r = i >> 6, cp = i & 63;
        float2 v = *(const float2*)(A + (size_t)(row0 + r) * 128 + 2 * cp);
        uint32_t h, l; bsplit(v.x, v.y, h, l);
        ap[r * 68 + cp] = make_uint2(h, l);
    }
    __syncthreads();
    float acc[4][4]{};
#pragma unroll
    for (int ks = 0; ks < 8; ++ks)
        pstep<4>(ap, 68, wm * 16, ks * 8, f3 + (ks * 16 + wn * 4) * 32, lane, acc);
    int lr0 = wm * 16 + g;
#pragma unroll
    for (int j = 0; j < 4; ++j) {
        int c = wn * 32 + j * 8 + 2 * t, ci = c >> 1;
        float bb0 = b3s[c], bb1 = b3s[c + 1];
        uint32_t h, l;
        bsplit(sspf(sspf(acc[j][0] + bb0)), sspf(sspf(acc[j][1] + bb1)), h, l);
        vp[lr0 * 68 + ci] = make_uint2(h, l);
        bsplit(sspf(sspf(acc[j][2] + bb0)), sspf(sspf(acc[j][3] + bb1)), h, l);
        vp[(lr0 + 8) * 68 + ci] = make_uint2(h, l);
    }
    __syncthreads();
    float a2[4][4]{};
#pragma unroll
    for (int ks = 0; ks < 8; ++ks)
        pstep<4>(vp, 68, wm * 16, ks * 8, f4 + (ks * 16 + wn * 4) * 32, lane, a2);
    int r0 = row0 + lr0, r1 = r0 + 8;
#pragma unroll
    for (int j = 0; j < 4; ++j) {
        int c = wn * 32 + j * 8 + 2 * t;
        float bb0 = b4s[c], bb1 = b4s[c + 1];
        *(float2*)(out + (size_t)r0 * 128 + c) = make_float2(a2[j][0] + bb0, a2[j][1] + bb1);
        *(float2*)(out + (size_t)r1 * 128 + c) = make_float2(a2[j][2] + bb0, a2[j][3] + bb1);
    }
}

// main10: compaction + fp16x2 MT2/NB4 tiles + direct-atomic segmented epilogue
__global__ __launch_bounds__(512, 1)
void main10(const float* __restrict__ fij, const float* __restrict__ rij,
            const int* __restrict__ nbrs, const float* __restrict__ nmask,
            const float* __restrict__ b1, const float* __restrict__ b2,
            const float4* __restrict__ w1g, const float4* __restrict__ w2g,
            const float* __restrict__ Y, float* __restrict__ V) {
    extern __shared__ __align__(16) float sm[];
    float4*   b1f = (float4*)sm;                   // 2048 f4
    float4*   b2f = (float4*)(sm + 8192);          // 4096 f4
    uint32_t* fjs = (uint32_t*)(sm + 24576);       // 128 x 36
    uint32_t* w1p = (uint32_t*)(sm + 29184);       // 128 x 68
    uint32_t* list = (uint32_t*)(sm + 37888);      // 3584
    int* nbs_t = (int*)(sm + 41472);               // 2 x 128
    int* ats_t = (int*)(sm + 41728);               // 2 x 128
    float* b1s = sm + 41984; float* b2s = sm + 42112;
    int* wred = (int*)(sm + 42240); int* wpre = (int*)(sm + 42256);
    int* cntp = (int*)(sm + 42272);
    int tid = threadIdx.x, lane = tid & 31, warp = tid >> 5;
    int wm = warp & 3, wn = warp >> 2, g = lane >> 2, t = lane & 3;
    int cta = blockIdx.x;
    int astart = cta * 55 + min(cta, 52);
    int natoms = 55 + (cta < 52 ? 1 : 0);

    for (int i = tid; i < 2048; i += 512) b1f[i] = w1g[i];
    for (int i = tid; i < 4096; i += 512) b2f[i] = w2g[i];
    if (tid < 128) { b1s[tid] = b1[tid]; b2s[tid] = b2[tid]; }
    for (int i = tid; i < 896; i += 512) {          // zero fjs pad (pairs 25..31)
        int r = i / 7, q = 1 + (i - r * 7);
        fjs[r * 36 + 24 + q] = 0u;
    }
    // ---- ordered compaction ----
    int rows_total = natoms * 64;
    uint32_t grbase = (uint32_t)astart * 64;
    int myc = 0; uint32_t kept[7];
#pragma unroll
    for (int k = 0; k < 7; ++k) {
        int rr = tid * 7 + k;
        if (rr < rows_total) {
            uint32_t gr = grbase + rr;
            if (rij[gr] <= 5.f && nmask[gr] > 0.5f) kept[myc++] = gr;
        }
    }
    int x = myc;
#pragma unroll
    for (int d = 1; d < 32; d <<= 1) { int y = __shfl_up_sync(~0u, x, d); if (lane >= d) x += y; }
    if (lane == 31) wred[warp] = x;
    __syncthreads();
    if (warp == 0) {
        int w = (lane < 16) ? wred[lane] : 0, xx = w;
#pragma unroll
        for (int d = 1; d < 16; d <<= 1) { int y = __shfl_up_sync(~0u, xx, d); if (lane >= d) xx += y; }
        if (lane < 16) wpre[lane] = xx - w;
        if (lane == 15) cntp[0] = xx;
    }
    __syncthreads();
    int base = wpre[warp] + (x - myc);
    for (int k = 0; k < myc; ++k) list[base + k] = kept[k];
    int cnt = cntp[0];
    int ntile = (cnt + 127) >> 7;
    for (int i = cnt + tid; i < ntile * 128; i += 512) list[i] = 0xFFFFFFFFu;
    __syncthreads();

    // preload tile 0
    for (int i = tid; i < 3200; i += 512) {
        int rr = i / 25, pr = i - rr * 25;
        uint32_t u = list[rr];
        size_t gr = (u == 0xFFFFFFFFu) ? 0 : (size_t)u;
        float2 v = *(const float2*)(fij + gr * 50 + 2 * pr);
        int q = pr & 7;
        fjs[rr * 36 + (pr >> 3) * 8 + (q & 3) * 2 + (q >> 2)] = pkh(v.x, v.y);
    }
    if (tid < 128) {
        uint32_t u = list[tid];
        if (u == 0xFFFFFFFFu) { ats_t[tid] = -1; nbs_t[tid] = 0; }
        else { ats_t[tid] = (int)(u >> 6); nbs_t[tid] = nbrs[u]; }
    }
    __syncthreads();

    for (int T = 0; T < ntile; ++T) {
        int buf = T & 1;
        // GEMM1 (K=64 padded) -> ssp -> w1p (fp16 packed)
        float a1[2][4][4]{};
#pragma unroll
        for (int ks = 0; ks < 4; ++ks)
            psf(fjs, 36, wm * 32, ks * 8, b1f + (ks * 16 + wn * 4) * 32, lane, a1);
#pragma unroll
        for (int mt = 0; mt < 2; ++mt) {
            int r0 = wm * 32 + mt * 16 + g, r1 = r0 + 8;
#pragma unroll
            for (int j = 0; j < 4; ++j) {
                int c = wn * 32 + j * 8 + 2 * t;
                int bofs = (2 * wn + (j >> 1)) * 8 + 2 * t + (j & 1);
                float bb0 = b1s[c], bb1 = b1s[c + 1];
                w1p[r0 * 68 + bofs] = pkh(sspf(a1[mt][j][0] * INV32 + bb0),
                                          sspf(a1[mt][j][1] * INV32 + bb1));
                w1p[r1 * 68 + bofs] = pkh(sspf(a1[mt][j][2] * INV32 + bb0),
                                          sspf(a1[mt][j][3] * INV32 + bb1));
            }
        }
        // prefetch tile T+1
        float2 pf[7]; int pa = -1, pn = 0;
        if (T + 1 < ntile) {
#pragma unroll
            for (int k = 0; k < 7; ++k) {
                int idx = tid + k * 512;
                if (idx < 3200) {
                    int rr = idx / 25, pr = idx - rr * 25;
                    uint32_t u = list[(T + 1) * 128 + rr];
                    size_t gr = (u == 0xFFFFFFFFu) ? 0 : (size_t)u;
                    pf[k] = *(const float2*)(fij + gr * 50 + 2 * pr);
                }
            }
            if (tid < 128) {
                uint32_t u = list[(T + 1) * 128 + tid];
                if (u != 0xFFFFFFFFu) { pa = (int)(u >> 6); pn = nbrs[u]; }
            }
        }
        __syncthreads();   // #1: w1p complete (all wn), fjs reads done
        // GEMM2 (K=128)
        float a2[2][4][4]{};
#pragma unroll
        for (int ks = 0; ks < 8; ++ks)
            psf(w1p, 68, wm * 32, ks * 8, b2f + (ks * 16 + wn * 4) * 32, lane, a2);
        // drain prefetch into fjs[T+1] + meta[buf^1]
        if (T + 1 < ntile) {
#pragma unroll
            for (int k = 0; k < 7; ++k) {
                int idx = tid + k * 512;
                if (idx < 3200) {
                    int rr = idx / 25, pr = idx - rr * 25;
                    int q = pr & 7;
                    fjs[rr * 36 + (pr >> 3) * 8 + (q & 3) * 2 + (q >> 2)] = pkh(pf[k].x, pf[k].y);
                }
            }
            if (tid < 128) { ats_t[(buf ^ 1) * 128 + tid] = pa; nbs_t[(buf ^ 1) * 128 + tid] = pn; }
        }
        // epi2: per-thread segmented merge over 4 sorted rows -> atomicAdd V
        {
            int c0 = wn * 32 + 2 * t;
            float s[8]; int cur = -1;
#pragma unroll
            for (int ri = 0; ri < 4; ++ri) {
                int mt = ri >> 1, h = ri & 1;
                int r = wm * 32 + mt * 16 + h * 8 + g;
                int a = ats_t[buf * 128 + r];
                float p[8];
                if (a >= 0) {
                    const float* yr = Y + ((size_t)(a >> 10) * 1024 + nbs_t[buf * 128 + r]) * 128;
#pragma unroll
                    for (int j = 0; j < 4; ++j) {
                        int c = c0 + j * 8;
                        float2 yv = *(const float2*)(yr + c);
                        p[2 * j]     = (a2[mt][j][h * 2]     * INV32 + b2s[c])     * yv.x;
                        p[2 * j + 1] = (a2[mt][j][h * 2 + 1] * INV32 + b2s[c + 1]) * yv.y;
                    }
                }
                if (a != cur) {
                    if (cur >= 0) {
#pragma unroll
                        for (int m = 0; m < 8; ++m)
                            atomicAdd(V + (size_t)cur * 128 + c0 + (m >> 1) * 8 + (m & 1), s[m]);
                    }
                    cur = a;
                    if (a >= 0) {
#pragma unroll
                        for (int m = 0; m < 8; ++m) s[m] = p[m];
                    }
                } else if (a >= 0) {
#pragma unroll
                    for (int m = 0; m < 8; ++m) s[m] += p[m];
                }
            }
            if (cur >= 0) {
#pragma unroll
                for (int m = 0; m < 8; ++m)
                    atomicAdd(V + (size_t)cur * 128 + c0 + (m >> 1) * 8 + (m & 1), s[m]);
            }
        }
        __syncthreads();   // #2: fjs[T+1]/meta visible; w1p free
    }
}

extern "C" void kernel_launch(void* const* d_in, const int* in_sizes, int n_in,
                              void* d_out, int out_size) {
    const float* x      = (const float*)d_in[0];
    const float* rij    = (const float*)d_in[1];
    const int*   nbrs   = (const int*)d_in[2];
    const float* nmask  = (const float*)d_in[3];
    const float* fij    = (const float*)d_in[4];
    const float* Win2f  = (const float*)d_in[5];
    const float* Wf1    = (const float*)d_in[6];
    const float* bf1    = (const float*)d_in[7];
    const float* Wf2    = (const float*)d_in[8];
    const float* bf2    = (const float*)d_in[9];
    const float* Wfout  = (const float*)d_in[10];
    const float* bfout  = (const float*)d_in[11];
    const float* Wdense = (const float*)d_in[12];
    const float* bdense = (const float*)d_in[13];
    float* out = (float*)d_out;

    cudaFuncSetAttribute(gemmB,  cudaFuncAttributeMaxDynamicSharedMemorySize, 100352);
    cudaFuncSetAttribute(gemmC,  cudaFuncAttributeMaxDynamicSharedMemorySize, 202752);
    cudaFuncSetAttribute(main10, cudaFuncAttributeMaxDynamicSharedMemorySize, 169216);

    void *py, *pv, *p0, *p1, *p2, *p3, *p4;
    cudaGetSymbolAddress(&py, g_y);
    cudaGetSymbolAddress(&pv, g_v);
    cudaGetSymbolAddress(&p0, g_wp0);
    cudaGetSymbolAddress(&p1, g_wp1);
    cudaGetSymbolAddress(&p2, g_wp2);
    cudaGetSymbolAddress(&p3, g_wp3);
    cudaGetSymbolAddress(&p4, g_wp4);

    pack5<<<576, 32>>>(Win2f, Wf1, Wf2, Wfout, Wdense,
                       (float4*)p0, (float4*)p1, (float4*)p2, (float4*)p3, (float4*)p4);
    zerov<<<512, 512>>>((float4*)pv);
    gemmB<<<128, 512, 100352>>>(x, (const float4*)p0, (float*)py);
    main10<<<148, 512, 169216>>>(fij, rij, nbrs, nmask, bf1, bf2,
                                 (const float4*)p1, (const float4*)p2,
                                 (const float*)py, (float*)pv);
    gemmC<<<128, 512, 202752>>>((const float*)pv, (const float4*)p3, (const float4*)p4,
                                bfout, bdense, out);
}

// round 16
// speedup vs baseline: 1.1748x; 1.1748x over previous
#include <cuda_runtime.h>
#include <cstdint>

__device__ float g_y[8192*128], g_v[8192*128];
__device__ float4 g_wp0[8*16*32], g_wp1[4*16*32], g_wp2[8*16*32],
                  g_wp3[8*16*32], g_wp4[8*16*32];

__device__ __forceinline__ uint32_t pkbf(float lo, float hi) {
    uint32_t r; asm("cvt.rn.bf16x2.f32 %0, %1, %2;" : "=r"(r) : "f"(hi), "f"(lo)); return r;
}
__device__ __forceinline__ void bsplit(float x0, float x1, uint32_t& h, uint32_t& l) {
    h = pkbf(x0, x1);
    float r0 = x0 - __uint_as_float(h << 16);
    float r1 = x1 - __uint_as_float(h & 0xffff0000u);
    l = pkbf(r0, r1);
}
__device__ __forceinline__ void mma16(float* c, const uint32_t* a, uint32_t b0, uint32_t b1) {
    asm volatile("mma.sync.aligned.m16n8k16.row.col.f32.bf16.bf16.f32 "
        "{%0,%1,%2,%3},{%4,%5,%6,%7},{%8,%9},{%0,%1,%2,%3};"
        : "+f"(c[0]), "+f"(c[1]), "+f"(c[2]), "+f"(c[3])
        : "r"(a[0]), "r"(a[1]), "r"(a[2]), "r"(a[3]), "r"(b0), "r"(b1));
}
__device__ __forceinline__ float sspf(float x) {
    float e = __expf(-fabsf(x));
    return fmaxf(x, 0.f) + __logf(1.f + e) - 0.69314718055994531f;
}

template <int NB>
__device__ __forceinline__ void pstep(const uint2* Ap, int lda, int m0, int kc,
                                      const float4* Bs, int lane, float (*acc)[4]) {
    int g = lane >> 2, t = lane & 3;
    const uint2* p0 = Ap + (m0 + g) * lda + kc + t;
    const uint2* p1 = p0 + 8 * lda;
    uint2 a0 = p0[0], a1 = p1[0], a2 = p0[4], a3 = p1[4];
    uint32_t ah[4] = {a0.x, a1.x, a2.x, a3.x};
    uint32_t al[4] = {a0.y, a1.y, a2.y, a3.y};
    float4 b[NB];
#pragma unroll
    for (int j = 0; j < NB; ++j) b[j] = Bs[j * 32 + lane];
#pragma unroll
    for (int j = 0; j < NB; ++j)
        mma16(acc[j], ah, __float_as_uint(b[j].x), __float_as_uint(b[j].z));
#pragma unroll
    for (int j = 0; j < NB; ++j)
        mma16(acc[j], ah, __float_as_uint(b[j].y), __float_as_uint(b[j].w));
#pragma unroll
    for (int j = 0; j < NB; ++j)
        mma16(acc[j], al, __float_as_uint(b[j].x), __float_as_uint(b[j].z));
}

__global__ void pack5(const float* w0, const float* w1, const float* w2,
                      const float* w3, const float* w4,
                      float4* o0, float4* o1, float4* o2, float4* o3, float4* o4) {
    int b = blockIdx.x, lane = threadIdx.x, kidx = b >> 4, nb = b & 15;
    const float* W; float4* D; int K, ks;
    if (kidx < 8)       { W = w0; D = o0; K = 128; ks = kidx;      }
    else if (kidx < 12) { W = w1; D = o1; K = 50;  ks = kidx - 8;  }
    else if (kidx < 20) { W = w2; D = o2; K = 128; ks = kidx - 12; }
    else if (kidx < 28) { W = w3; D = o3; K = 128; ks = kidx - 20; }
    else                { W = w4; D = o4; K = 128; ks = kidx - 28; }
    int g = lane >> 2, t = lane & 3, n = nb * 8 + g, k0 = ks * 16 + 2 * t;
    float a = (k0 < K) ? W[n * K + k0] : 0.f, b1 = (k0 + 1 < K) ? W[n * K + k0 + 1] : 0.f;
    float c = (k0 + 8 < K) ? W[n * K + k0 + 8] : 0.f, d = (k0 + 9 < K) ? W[n * K + k0 + 9] : 0.f;
    uint32_t h0, l0, h1, l1;
    bsplit(a, b1, h0, l0); bsplit(c, d, h1, l1);
    D[(ks * 16 + nb) * 32 + lane] = make_float4(__uint_as_float(h0), __uint_as_float(l0),
                                                __uint_as_float(h1), __uint_as_float(l1));
}

// y = A @ W0^T; also zeroes V (fused former zerov)
__global__ __launch_bounds__(512, 1)
void gemmB(const float* __restrict__ A, const float4* __restrict__ Bp,
           float* __restrict__ out, float4* __restrict__ vz) {
    extern __shared__ __align__(16) float sm[];
    float4* bf = (float4*)sm;
    uint2*  ap = (uint2*)(sm + 16384);
    int tid = threadIdx.x, lane = tid & 31, warp = tid >> 5;
    int wm = warp & 3, wn = warp >> 2, g = lane >> 2, t = lane & 3;
    int row0 = blockIdx.x * 64;
    {   // zero g_v: 262144 float4 over 65536 threads -> 4 each
        size_t gt = (size_t)blockIdx.x * 512 + tid;
        float4 z = make_float4(0.f, 0.f, 0.f, 0.f);
#pragma unroll
        for (int k = 0; k < 4; ++k) vz[gt * 4 + k] = z;
    }
    for (int i = tid; i < 4096; i += 512) bf[i] = Bp[i];
    for (int i = tid; i < 4096; i += 512) {
        int r = i >> 6, cp = i & 63;
        float2 v = *(const float2*)(A + (size_t)(row0 + r) * 128 + 2 * cp);
        uint32_t h, l; bsplit(v.x, v.y, h, l);
        ap[r * 68 + cp] = make_uint2(h, l);
    }
    __syncthreads();
    float acc[4][4]{};
#pragma unroll
    for (int ks = 0; ks < 8; ++ks)
        pstep<4>(ap, 68, wm * 16, ks * 8, bf + (ks * 16 + wn * 4) * 32, lane, acc);
    int r0 = row0 + wm * 16 + g, r1 = r0 + 8;
#pragma unroll
    for (int j = 0; j < 4; ++j) {
        int c = wn * 32 + j * 8 + 2 * t;
        *(float2*)(out + (size_t)r0 * 128 + c) = make_float2(acc[j][0], acc[j][1]);
        *(float2*)(out + (size_t)r1 * 128 + c) = make_float2(acc[j][2], acc[j][3]);
    }
}

__global__ __launch_bounds__(512, 1)
void gemmC(const float* __restrict__ A, const float4* __restrict__ B3,
           const float4* __restrict__ B4, const float* __restrict__ b3,
           const float* __restrict__ b4, float* __restrict__ out) {
    extern __shared__ __align__(16) float sm[];
    float4* f3 = (float4*)sm;
    float4* f4 = (float4*)(sm + 16384);
    uint2*  ap = (uint2*)(sm + 32768);
    uint2*  vp = (uint2*)(sm + 41472);
    float* b3s = sm + 50176; float* b4s = sm + 50304;
    int tid = threadIdx.x, lane = tid & 31, warp = tid >> 5;
    int wm = warp & 3, wn = warp >> 2, g = lane >> 2, t = lane & 3;
    int row0 = blockIdx.x * 64;
    for (int i = tid; i < 4096; i += 512) { f3[i] = B3[i]; f4[i] = B4[i]; }
    if (tid < 128) { b3s[tid] = b3[tid]; b4s[tid] = b4[tid]; }
    for (int i = tid; i < 4096; i += 512) {
        int r = i >> 6, cp = i & 63;
        float2 v = *(const float2*)(A + (size_t)(row0 + r) * 128 + 2 * cp);
        uint32_t h, l; bsplit(v.x, v.y, h, l);
        ap[r * 68 + cp] = make_uint2(h, l);
    }
    __syncthreads();
    float acc[4][4]{};
#pragma unroll
    for (int ks = 0; ks < 8; ++ks)
        pstep<4>(ap, 68, wm * 16, ks * 8, f3 + (ks * 16 + wn * 4) * 32, lane, acc);
    int lr0 = wm * 16 + g;
#pragma unroll
    for (int j = 0; j < 4; ++j) {
        int c = wn * 32 + j * 8 + 2 * t, ci = c >> 1;
        float bb0 = b3s[c], bb1 = b3s[c + 1];
        uint32_t h, l;
        bsplit(sspf(sspf(acc[j][0] + bb0)), sspf(sspf(acc[j][1] + bb1)), h, l);
        vp[lr0 * 68 + ci] = make_uint2(h, l);
        bsplit(sspf(sspf(acc[j][2] + bb0)), sspf(sspf(acc[j][3] + bb1)), h, l);
        vp[(lr0 + 8) * 68 + ci] = make_uint2(h, l);
    }
    __syncthreads();
    float a2[4][4]{};
#pragma unroll
    for (int ks = 0; ks < 8; ++ks)
        pstep<4>(vp, 68, wm * 16, ks * 8, f4 + (ks * 16 + wn * 4) * 32, lane, a2);
    int r0 = row0 + lr0, r1 = r0 + 8;
#pragma unroll
    for (int j = 0; j < 4; ++j) {
        int c = wn * 32 + j * 8 + 2 * t;
        float bb0 = b4s[c], bb1 = b4s[c + 1];
        *(float2*)(out + (size_t)r0 * 128 + c) = make_float2(a2[j][0] + bb0, a2[j][1] + bb1);
        *(float2*)(out + (size_t)r1 * 128 + c) = make_float2(a2[j][2] + bb0, a2[j][3] + bb1);
    }
}

// main11: main9 (223us config) + named-barrier race fix
__global__ __launch_bounds__(512, 1)
void main11(const float* __restrict__ fij, const float* __restrict__ rij,
            const int* __restrict__ nbrs, const float* __restrict__ nmask,
            const float* __restrict__ b1, const float* __restrict__ b2,
            const float4* __restrict__ w1g, const float4* __restrict__ w2g,
            const float* __restrict__ Y, float* __restrict__ V) {
    extern __shared__ __align__(16) float sm[];
    float4*   b1f = (float4*)sm;
    float4*   b2f = (float4*)(sm + 8192);
    uint2*    fjs = (uint2*)(sm + 24576);          // 128 x 34
    uint2*    w1p = (uint2*)(sm + 33280);          // 128 x 66
    uint32_t* list = (uint32_t*)(sm + 50176);      // 3584
    int*   nbs_t = (int*)(sm + 53760);             // 2 x 128
    int*   ats_t = (int*)(sm + 54016);             // 2 x 128
    float* b1s = sm + 54272; float* b2s = sm + 54400;
    int* wred = (int*)(sm + 54528); int* wpre = (int*)(sm + 54544);
    int* cntp = (int*)(sm + 54560);
    int tid = threadIdx.x, lane = tid & 31, warp = tid >> 5;
    int wm = warp & 7, wn = warp >> 3, g = lane >> 2, t = lane & 3;
    int cta = blockIdx.x;
    int astart = cta * 55 + min(cta, 52);
    int natoms = 55 + (cta < 52 ? 1 : 0);

    for (int i = tid; i < 2048; i += 512) b1f[i] = w1g[i];
    for (int i = tid; i < 4096; i += 512) b2f[i] = w2g[i];
    if (tid < 128) { b1s[tid] = b1[tid]; b2s[tid] = b2[tid]; }
    for (int i = tid; i < 896; i += 512) {
        int r = i / 7, c = 25 + (i - r * 7);
        fjs[r * 34 + c] = make_uint2(0u, 0u);
    }
    // ---- ordered compaction of surviving rows ----
    int rows_total = natoms * 64;
    uint32_t grbase = (uint32_t)astart * 64;
    int myc = 0; uint32_t kept[7];
#pragma unroll
    for (int k = 0; k < 7; ++k) {
        int rr = tid * 7 + k;
        if (rr < rows_total) {
            uint32_t gr = grbase + rr;
            if (rij[gr] <= 5.f && nmask[gr] > 0.5f) kept[myc++] = gr;
        }
    }
    int x = myc;
#pragma unroll
    for (int d = 1; d < 32; d <<= 1) { int y = __shfl_up_sync(~0u, x, d); if (lane >= d) x += y; }
    if (lane == 31) wred[warp] = x;
    __syncthreads();
    if (warp == 0) {
        int w = (lane < 16) ? wred[lane] : 0, xx = w;
#pragma unroll
        for (int d = 1; d < 16; d <<= 1) { int y = __shfl_up_sync(~0u, xx, d); if (lane >= d) xx += y; }
        if (lane < 16) wpre[lane] = xx - w;
        if (lane == 15) cntp[0] = xx;
    }
    __syncthreads();
    int base = wpre[warp] + (x - myc);
    for (int k = 0; k < myc; ++k) list[base + k] = kept[k];
    int cnt = cntp[0];
    int ntile = (cnt + 127) >> 7;
    for (int i = cnt + tid; i < ntile * 128; i += 512) list[i] = 0xFFFFFFFFu;
    __syncthreads();

    // preload tile 0
    for (int i = tid; i < 3200; i += 512) {
        int rr = i / 25, pr = i - rr * 25;
        uint32_t u = list[rr];
        size_t gr = (u == 0xFFFFFFFFu) ? 0 : (size_t)u;
        float2 v = *(const float2*)(fij + gr * 50 + 2 * pr);
        uint32_t h, l; bsplit(v.x, v.y, h, l);
        fjs[rr * 34 + pr] = make_uint2(h, l);
    }
    if (tid < 128) {
        uint32_t u = list[tid];
        if (u == 0xFFFFFFFFu) { ats_t[tid] = -1; nbs_t[tid] = 0; }
        else { ats_t[tid] = (int)(u >> 6); nbs_t[tid] = nbrs[u]; }
    }
    __syncthreads();

    for (int T = 0; T < ntile; ++T) {
        int buf = T & 1;
        // GEMM1 (K=64 padded) + b1 + ssp -> packed w1p
        {
            float a1[8][4]{};
#pragma unroll
            for (int ks = 0; ks < 4; ++ks)
                pstep<8>(fjs, 34, wm * 16, ks * 8, b1f + (ks * 16 + wn * 8) * 32, lane, a1);
            int r0 = wm * 16 + g;
#pragma unroll
            for (int j = 0; j < 8; ++j) {
                int c = wn * 64 + j * 8 + 2 * t, ci = c >> 1;
                float bb0 = b1s[c], bb1 = b1s[c + 1];
                uint32_t h, l;
                bsplit(sspf(a1[j][0] + bb0), sspf(a1[j][1] + bb1), h, l);
                w1p[r0 * 66 + ci] = make_uint2(h, l);
                bsplit(sspf(a1[j][2] + bb0), sspf(a1[j][3] + bb1), h, l);
                w1p[(r0 + 8) * 66 + ci] = make_uint2(h, l);
            }
        }
        // race fix: warps (wm, wn=0) and (wm, wn=1) = warps wm, wm+8 both write the
        // wm-row-slab of w1p (different columns); GEMM2 below reads all columns.
        asm volatile("bar.sync %0, %1;" :: "r"(wm + 1), "r"(64) : "memory");
        // prefetch tile T+1 (fij rows + meta) into registers
        float2 pf[7]; int pa = -1, pn = 0;
        if (T + 1 < ntile) {
#pragma unroll
            for (int k = 0; k < 7; ++k) {
                int idx = tid + k * 512;
                if (idx < 3200) {
                    int rr = idx / 25, pr = idx - rr * 25;
                    uint32_t u = list[(T + 1) * 128 + rr];
                    size_t gr = (u == 0xFFFFFFFFu) ? 0 : (size_t)u;
                    pf[k] = *(const float2*)(fij + gr * 50 + 2 * pr);
                }
            }
            if (tid < 128) {
                uint32_t u = list[(T + 1) * 128 + tid];
                if (u != 0xFFFFFFFFu) { pa = (int)(u >> 6); pn = nbrs[u]; }
            }
        }
        // GEMM2 (K=128), reads own w1p row-slab
        float a2[8][4]{};
#pragma unroll
        for (int ks = 0; ks < 8; ++ks)
            pstep<8>(w1p, 66, wm * 16, ks * 8, b2f + (ks * 16 + wn * 8) * 32, lane, a2);
        // epi2: p = (d + b2) * y[nb] -> pw (own slab, per-lane same rows)
        {
            float* pw = (float*)w1p;
            int r0 = wm * 16 + g, r1 = r0 + 8;
            int aA = ats_t[buf * 128 + r0], aB = ats_t[buf * 128 + r1];
            size_t yi0 = (aA >= 0) ? ((size_t)(aA >> 10) * 1024 + nbs_t[buf * 128 + r0]) : 0;
            size_t yi1 = (aB >= 0) ? ((size_t)(aB >> 10) * 1024 + nbs_t[buf * 128 + r1]) : 0;
            const float* y0 = Y + yi0 * 128;
            const float* y1 = Y + yi1 * 128;
#pragma unroll
            for (int j = 0; j < 8; ++j) {
                int c = wn * 64 + j * 8 + 2 * t;
                float2 ya = *(const float2*)(y0 + c);
                float2 yc = *(const float2*)(y1 + c);
                float bb0 = b2s[c], bb1 = b2s[c + 1];
                *(float2*)(pw + r0 * 132 + c) =
                    make_float2((a2[j][0] + bb0) * ya.x, (a2[j][1] + bb1) * ya.y);
                *(float2*)(pw + r1 * 132 + c) =
                    make_float2((a2[j][2] + bb0) * yc.x, (a2[j][3] + bb1) * yc.y);
            }
        }
        __syncthreads();    // #1: pw visible to all; fjs free
        // drain prefetch: fjs[T+1] + meta[buf^1]
        if (T + 1 < ntile) {
#pragma unroll
            for (int k = 0; k < 7; ++k) {
                int idx = tid + k * 512;
                if (idx < 3200) {
                    int rr = idx / 25, pr = idx - rr * 25;
                    uint32_t h, l; bsplit(pf[k].x, pf[k].y, h, l);
                    fjs[rr * 34 + pr] = make_uint2(h, l);
                }
            }
            if (tid < 128) { ats_t[(buf ^ 1) * 128 + tid] = pa; nbs_t[(buf ^ 1) * 128 + tid] = pn; }
        }
        // segmented reduce over atom-sorted rows -> atomicAdd V
        {
            const float* pw = (const float*)w1p;
            int f = tid & 127, q = tid >> 7;
            float s = 0.f; int cur = ats_t[buf * 128 + q * 32];
            for (int r = q * 32; r < q * 32 + 32; ++r) {
                int a = ats_t[buf * 128 + r];
                if (a != cur) {
                    if (cur >= 0) atomicAdd(V + (size_t)cur * 128 + f, s);
                    s = 0.f; cur = a;
                }
                s += pw[r * 132 + f];
            }
            if (cur >= 0) atomicAdd(V + (size_t)cur * 128 + f, s);
        }
        __syncthreads();    // #2: pw free; fjs[T+1] ready
    }
}

extern "C" void kernel_launch(void* const* d_in, const int* in_sizes, int n_in,
                              void* d_out, int out_size) {
    const float* x      = (const float*)d_in[0];
    const float* rij    = (const float*)d_in[1];
    const int*   nbrs   = (const int*)d_in[2];
    const float* nmask  = (const float*)d_in[3];
    const float* fij    = (const float*)d_in[4];
    const float* Win2f  = (const float*)d_in[5];
    const float* Wf1    = (const float*)d_in[6];
    const float* bf1    = (const float*)d_in[7];
    const float* Wf2    = (const float*)d_in[8];
    const float* bf2    = (const float*)d_in[9];
    const float* Wfout  = (const float*)d_in[10];
    const float* bfout  = (const float*)d_in[11];
    const float* Wdense = (const float*)d_in[12];
    const float* bdense = (const float*)d_in[13];
    float* out = (float*)d_out;

    cudaFuncSetAttribute(gemmB,  cudaFuncAttributeMaxDynamicSharedMemorySize, 100352);
    cudaFuncSetAttribute(gemmC,  cudaFuncAttributeMaxDynamicSharedMemorySize, 202752);
    cudaFuncSetAttribute(main11, cudaFuncAttributeMaxDynamicSharedMemorySize, 218304);

    void *py, *pv, *p0, *p1, *p2, *p3, *p4;
    cudaGetSymbolAddress(&py, g_y);
    cudaGetSymbolAddress(&pv, g_v);
    cudaGetSymbolAddress(&p0, g_wp0);
    cudaGetSymbolAddress(&p1, g_wp1);
    cudaGetSymbolAddress(&p2, g_wp2);
    cudaGetSymbolAddress(&p3, g_wp3);
    cudaGetSymbolAddress(&p4, g_wp4);

    pack5<<<576, 32>>>(Win2f, Wf1, Wf2, Wfout, Wdense,
                       (float4*)p0, (float4*)p1, (float4*)p2, (float4*)p3, (float4*)p4);
    gemmB<<<128, 512, 100352>>>(x, (const float4*)p0, (float*)py, (float4*)pv);
    main11<<<148, 512, 218304>>>(fij, rij, nbrs, nmask, bf1, bf2,
                                 (const float4*)p1, (const float4*)p2,
                                 (const float*)py, (float*)pv);
    gemmC<<<128, 512, 202752>>>((const float*)pv, (const float4*)p3, (const float4*)p4,
                                bfout, bdense, out);
}

// round 17
// speedup vs baseline: 1.4026x; 1.1939x over previous
#include <cuda_runtime.h>
#include <cuda_fp16.h>
#include <cstdint>

__device__ float g_y[8192*128], g_v[8192*128];
__device__ float4 g_wp0[8*16*32], g_wp1[4*16*32], g_wp2[8*16*32],
                  g_wp3[8*16*32], g_wp4[8*16*32];
__device__ uint32_t g_list[148 * 3584];

#define INV32 0.03125f

__device__ __forceinline__ uint32_t pkbf(float lo, float hi) {
    uint32_t r; asm("cvt.rn.bf16x2.f32 %0, %1, %2;" : "=r"(r) : "f"(hi), "f"(lo)); return r;
}
__device__ __forceinline__ void bsplit(float x0, float x1, uint32_t& h, uint32_t& l) {
    h = pkbf(x0, x1);
    float r0 = x0 - __uint_as_float(h << 16);
    float r1 = x1 - __uint_as_float(h & 0xffff0000u);
    l = pkbf(r0, r1);
}
__device__ __forceinline__ uint32_t pkh(float x0, float x1) {
    __half2 hh = __floats2half2_rn(x0, x1);
    return *(uint32_t*)&hh;
}
__device__ __forceinline__ void hsplit(float x0, float x1, uint32_t& h, uint32_t& l) {
    __half2 hh = __floats2half2_rn(x0, x1);
    float2 bb = __half22float2(hh);
    h = *(uint32_t*)&hh;
    l = pkh(x0 - bb.x, x1 - bb.y);
}
__device__ __forceinline__ void mma16(float* c, const uint32_t* a, uint32_t b0, uint32_t b1) {
    asm volatile("mma.sync.aligned.m16n8k16.row.col.f32.bf16.bf16.f32 "
        "{%0,%1,%2,%3},{%4,%5,%6,%7},{%8,%9},{%0,%1,%2,%3};"
        : "+f"(c[0]), "+f"(c[1]), "+f"(c[2]), "+f"(c[3])
        : "r"(a[0]), "r"(a[1]), "r"(a[2]), "r"(a[3]), "r"(b0), "r"(b1));
}
__device__ __forceinline__ void mma16f(float* c, const uint32_t* a, uint32_t b0, uint32_t b1) {
    asm volatile("mma.sync.aligned.m16n8k16.row.col.f32.f16.f16.f32 "
        "{%0,%1,%2,%3},{%4,%5,%6,%7},{%8,%9},{%0,%1,%2,%3};"
        : "+f"(c[0]), "+f"(c[1]), "+f"(c[2]), "+f"(c[3])
        : "r"(a[0]), "r"(a[1]), "r"(a[2]), "r"(a[3]), "r"(b0), "r"(b1));
}
__device__ __forceinline__ float sspf(float x) {
    float e = __expf(-fabsf(x));
    return fmaxf(x, 0.f) + __logf(1.f + e) - 0.69314718055994531f;
}

// ---- bf16x3 pstep (validated; gemmB/gemmC) ----
template <int NB>
__device__ __forceinline__ void pstep(const uint2* Ap, int lda, int m0, int kc,
                                      const float4* Bs, int lane, float (*acc)[4]) {
    int g = lane >> 2, t = lane & 3;
    const uint2* p0 = Ap + (m0 + g) * lda + kc + t;
    const uint2* p1 = p0 + 8 * lda;
    uint2 a0 = p0[0], a1 = p1[0], a2 = p0[4], a3 = p1[4];
    uint32_t ah[4] = {a0.x, a1.x, a2.x, a3.x};
    uint32_t al[4] = {a0.y, a1.y, a2.y, a3.y};
    float4 b[NB];
#pragma unroll
    for (int j = 0; j < NB; ++j) b[j] = Bs[j * 32 + lane];
#pragma unroll
    for (int j = 0; j < NB; ++j)
        mma16(acc[j], ah, __float_as_uint(b[j].x), __float_as_uint(b[j].z));
#pragma unroll
    for (int j = 0; j < NB; ++j)
        mma16(acc[j], ah, __float_as_uint(b[j].y), __float_as_uint(b[j].w));
#pragma unroll
    for (int j = 0; j < NB; ++j)
        mma16(acc[j], al, __float_as_uint(b[j].x), __float_as_uint(b[j].z));
}

// ---- fp16x2 step: A single-fp16 (t,t+4 interleaved), B fp16 hi/lo, 16 mma ----
__device__ __forceinline__ void psf8(const uint32_t* Ap, int lda, int m0, int kc,
                                     const float4* Bs, int lane, float (*acc)[4]) {
    int g = lane >> 2, t = lane & 3;
    const uint32_t* pr = Ap + (m0 + g) * lda + kc + 2 * t;
    uint2 v0 = *(const uint2*)pr;
    uint2 v1 = *(const uint2*)(pr + 8 * lda);
    uint32_t a[4] = {v0.x, v1.x, v0.y, v1.y};
    float4 b[8];
#pragma unroll
    for (int j = 0; j < 8; ++j) b[j] = Bs[j * 32 + lane];
#pragma unroll
    for (int j = 0; j < 8; ++j)
        mma16f(acc[j], a, __float_as_uint(b[j].x), __float_as_uint(b[j].z));
#pragma unroll
    for (int j = 0; j < 8; ++j)
        mma16f(acc[j], a, __float_as_uint(b[j].y), __float_as_uint(b[j].w));
}

// pack: W1/W2 -> fp16 hi/lo x32; W0/W3/W4 -> bf16 hi/lo
__global__ void pack5(const float* w0, const float* w1, const float* w2,
                      const float* w3, const float* w4,
                      float4* o0, float4* o1, float4* o2, float4* o3, float4* o4) {
    int b = blockIdx.x, lane = threadIdx.x, kidx = b >> 4, nb = b & 15;
    const float* W; float4* D; int K, ks, fp = 0;
    if (kidx < 8)       { W = w0; D = o0; K = 128; ks = kidx;      }
    else if (kidx < 12) { W = w1; D = o1; K = 50;  ks = kidx - 8;  fp = 1; }
    else if (kidx < 20) { W = w2; D = o2; K = 128; ks = kidx - 12; fp = 1; }
    else if (kidx < 28) { W = w3; D = o3; K = 128; ks = kidx - 20; }
    else                { W = w4; D = o4; K = 128; ks = kidx - 28; }
    int g = lane >> 2, t = lane & 3, n = nb * 8 + g, k0 = ks * 16 + 2 * t;
    float a = (k0 < K) ? W[n * K + k0] : 0.f, b1 = (k0 + 1 < K) ? W[n * K + k0 + 1] : 0.f;
    float c = (k0 + 8 < K) ? W[n * K + k0 + 8] : 0.f, d = (k0 + 9 < K) ? W[n * K + k0 + 9] : 0.f;
    uint32_t h0, l0, h1, l1;
    if (fp) { hsplit(a * 32.f, b1 * 32.f, h0, l0); hsplit(c * 32.f, d * 32.f, h1, l1); }
    else    { bsplit(a, b1, h0, l0); bsplit(c, d, h1, l1); }
    D[(ks * 16 + nb) * 32 + lane] = make_float4(__uint_as_float(h0), __uint_as_float(l0),
                                                __uint_as_float(h1), __uint_as_float(l1));
}

// y = A @ W0^T; also zeroes V
__global__ __launch_bounds__(512, 1)
void gemmB(const float* __restrict__ A, const float4* __restrict__ Bp,
           float* __restrict__ out, float4* __restrict__ vz) {
    extern __shared__ __align__(16) float sm[];
    float4* bf = (float4*)sm;
    uint2*  ap = (uint2*)(sm + 16384);
    int tid = threadIdx.x, lane = tid & 31, warp = tid >> 5;
    int wm = warp & 3, wn = warp >> 2, g = lane >> 2, t = lane & 3;
    int row0 = blockIdx.x * 64;
    {
        size_t gt = (size_t)blockIdx.x * 512 + tid;
        float4 z = make_float4(0.f, 0.f, 0.f, 0.f);
#pragma unroll
        for (int k = 0; k < 4; ++k) vz[gt * 4 + k] = z;
    }
    for (int i = tid; i < 4096; i += 512) bf[i] = Bp[i];
    for (int i = tid; i < 4096; i += 512) {
        int r = i >> 6, cp = i & 63;
        float2 v = *(const float2*)(A + (size_t)(row0 + r) * 128 + 2 * cp);
        uint32_t h, l; bsplit(v.x, v.y, h, l);
        ap[r * 68 + cp] = make_uint2(h, l);
    }
    __syncthreads();
    float acc[4][4]{};
#pragma unroll
    for (int ks = 0; ks < 8; ++ks)
        pstep<4>(ap, 68, wm * 16, ks * 8, bf + (ks * 16 + wn * 4) * 32, lane, acc);
    int r0 = row0 + wm * 16 + g, r1 = r0 + 8;
#pragma unroll
    for (int j = 0; j < 4; ++j) {
        int c = wn * 32 + j * 8 + 2 * t;
        *(float2*)(out + (size_t)r0 * 128 + c) = make_float2(acc[j][0], acc[j][1]);
        *(float2*)(out + (size_t)r1 * 128 + c) = make_float2(acc[j][2], acc[j][3]);
    }
}

__global__ __launch_bounds__(512, 1)
void gemmC(const float* __restrict__ A, const float4* __restrict__ B3,
           const float4* __restrict__ B4, const float* __restrict__ b3,
           const float* __restrict__ b4, float* __restrict__ out) {
    extern __shared__ __align__(16) float sm[];
    float4* f3 = (float4*)sm;
    float4* f4 = (float4*)(sm + 16384);
    uint2*  ap = (uint2*)(sm + 32768);
    uint2*  vp = (uint2*)(sm + 41472);
    float* b3s = sm + 50176; float* b4s = sm + 50304;
    int tid = threadIdx.x, lane = tid & 31, warp = tid >> 5;
    int wm = warp & 3, wn = warp >> 2, g = lane >> 2, t = lane & 3;
    int row0 = blockIdx.x * 64;
    for (int i = tid; i < 4096; i += 512) { f3[i] = B3[i]; f4[i] = B4[i]; }
    if (tid < 128) { b3s[tid] = b3[tid]; b4s[tid] = b4[tid]; }
    for (int i = tid; i < 4096; i += 512) {
        int r = i >> 6, cp = i & 63;
        float2 v = *(const float2*)(A + (size_t)(row0 + r) * 128 + 2 * cp);
        uint32_t h, l; bsplit(v.x, v.y, h, l);
        ap[r * 68 + cp] = make_uint2(h, l);
    }
    __syncthreads();
    float acc[4][4]{};
#pragma unroll
    for (int ks = 0; ks < 8; ++ks)
        pstep<4>(ap, 68, wm * 16, ks * 8, f3 + (ks * 16 + wn * 4) * 32, lane, acc);
    int lr0 = wm * 16 + g;
#pragma unroll
    for (int j = 0; j < 4; ++j) {
        int c = wn * 32 + j * 8 + 2 * t, ci = c >> 1;
        float bb0 = b3s[c], bb1 = b3s[c + 1];
        uint32_t h, l;
        bsplit(sspf(sspf(acc[j][0] + bb0)), sspf(sspf(acc[j][1] + bb1)), h, l);
        vp[lr0 * 68 + ci] = make_uint2(h, l);
        bsplit(sspf(sspf(acc[j][2] + bb0)), sspf(sspf(acc[j][3] + bb1)), h, l);
        vp[(lr0 + 8) * 68 + ci] = make_uint2(h, l);
    }
    __syncthreads();
    float a2[4][4]{};
#pragma unroll
    for (int ks = 0; ks < 8; ++ks)
        pstep<4>(vp, 68, wm * 16, ks * 8, f4 + (ks * 16 + wn * 4) * 32, lane, a2);
    int r0 = row0 + lr0, r1 = r0 + 8;
#pragma unroll
    for (int j = 0; j < 4; ++j) {
        int c = wn * 32 + j * 8 + 2 * t;
        float bb0 = b4s[c], bb1 = b4s[c + 1];
        *(float2*)(out + (size_t)r0 * 128 + c) = make_float2(a2[j][0] + bb0, a2[j][1] + bb1);
        *(float2*)(out + (size_t)r1 * 128 + c) = make_float2(a2[j][2] + bb0, a2[j][3] + bb1);
    }
}

// main12: main11 structure + fp16x2 numerics (A single fp16, B fp16 hi/lo x32)
__global__ __launch_bounds__(512, 1)
void main12(const float* __restrict__ fij, const float* __restrict__ rij,
            const int* __restrict__ nbrs, const float* __restrict__ nmask,
            const float* __restrict__ b1, const float* __restrict__ b2,
            const float4* __restrict__ w1g, const float4* __restrict__ w2g,
            const float* __restrict__ Y, float* __restrict__ V,
            uint32_t* __restrict__ glist) {
    extern __shared__ __align__(16) float sm[];
    float4*   b1f = (float4*)sm;                   // 32KB
    float4*   b2f = (float4*)(sm + 8192);          // 64KB
    uint32_t* fjs = (uint32_t*)(sm + 24576);       // 128 x 36 (18KB)
    uint32_t* w1p = (uint32_t*)(sm + 29184);       // 128 x 68 (34.8KB)
    float*    pw  = sm + 37888;                    // 128 x 132 (67.5KB)
    int*   nbs_t = (int*)(sm + 54784);             // 2 x 128
    int*   ats_t = (int*)(sm + 55040);             // 2 x 128
    float* b1s = sm + 55296; float* b2s = sm + 55424;
    int* wred = (int*)(sm + 55552); int* wpre = (int*)(sm + 55568);
    int* cntp = (int*)(sm + 55584);
    int tid = threadIdx.x, lane = tid & 31, warp = tid >> 5;
    int wm = warp & 7, wn = warp >> 3, g = lane >> 2, t = lane & 3;
    int cta = blockIdx.x;
    int astart = cta * 55 + min(cta, 52);
    int natoms = 55 + (cta < 52 ? 1 : 0);
    uint32_t* list = glist + (size_t)cta * 3584;

    for (int i = tid; i < 2048; i += 512) b1f[i] = w1g[i];
    for (int i = tid; i < 4096; i += 512) b2f[i] = w2g[i];
    if (tid < 128) { b1s[tid] = b1[tid]; b2s[tid] = b2[tid]; }
    for (int i = tid; i < 896; i += 512) {          // zero fjs pad pairs 25..31
        int r = i / 7, q = 1 + (i - r * 7);         // q = 1..7 within group 3
        fjs[r * 36 + 24 + (q & 3) * 2 + (q >> 2)] = 0u;
    }
    // ---- ordered compaction -> global list ----
    int rows_total = natoms * 64;
    uint32_t grbase = (uint32_t)astart * 64;
    int myc = 0; uint32_t kept[7];
#pragma unroll
    for (int k = 0; k < 7; ++k) {
        int rr = tid * 7 + k;
        if (rr < rows_total) {
            uint32_t gr = grbase + rr;
            if (rij[gr] <= 5.f && nmask[gr] > 0.5f) kept[myc++] = gr;
        }
    }
    int x = myc;
#pragma unroll
    for (int d = 1; d < 32; d <<= 1) { int y = __shfl_up_sync(~0u, x, d); if (lane >= d) x += y; }
    if (lane == 31) wred[warp] = x;
    __syncthreads();
    if (warp == 0) {
        int w = (lane < 16) ? wred[lane] : 0, xx = w;
#pragma unroll
        for (int d = 1; d < 16; d <<= 1) { int y = __shfl_up_sync(~0u, xx, d); if (lane >= d) xx += y; }
        if (lane < 16) wpre[lane] = xx - w;
        if (lane == 15) cntp[0] = xx;
    }
    __syncthreads();
    int base = wpre[warp] + (x - myc);
    for (int k = 0; k < myc; ++k) list[base + k] = kept[k];
    int cnt = cntp[0];
    int ntile = (cnt + 127) >> 7;
    for (int i = cnt + tid; i < ntile * 128; i += 512) list[i] = 0xFFFFFFFFu;
    __syncthreads();

    // preload tile 0
    for (int i = tid; i < 3200; i += 512) {
        int rr = i / 25, pr = i - rr * 25;
        uint32_t u = list[rr];
        size_t gr = (u == 0xFFFFFFFFu) ? 0 : (size_t)u;
        float2 v = *(const float2*)(fij + gr * 50 + 2 * pr);
        int q = pr & 7;
        fjs[rr * 36 + (pr >> 3) * 8 + (q & 3) * 2 + (q >> 2)] = pkh(v.x, v.y);
    }
    if (tid < 128) {
        uint32_t u = list[tid];
        if (u == 0xFFFFFFFFu) { ats_t[tid] = -1; nbs_t[tid] = 0; }
        else { ats_t[tid] = (int)(u >> 6); nbs_t[tid] = nbrs[u]; }
    }
    __syncthreads();

    for (int T = 0; T < ntile; ++T) {
        int buf = T & 1;
        // GEMM1 (K=64 padded) -> +b1, ssp -> fp16 w1p
        {
            float a1[8][4]{};
#pragma unroll
            for (int ks = 0; ks < 4; ++ks)
                psf8(fjs, 36, wm * 16, ks * 8, b1f + (ks * 16 + wn * 8) * 32, lane, a1);
            int r0 = wm * 16 + g;
#pragma unroll
            for (int j = 0; j < 8; ++j) {
                int c = wn * 64 + j * 8 + 2 * t;
                int idx = (wn * 4 + (j >> 1)) * 8 + 2 * t + (j & 1);
                float bb0 = b1s[c], bb1 = b1s[c + 1];
                w1p[r0 * 68 + idx] = pkh(sspf(a1[j][0] * INV32 + bb0),
                                         sspf(a1[j][1] * INV32 + bb1));
                w1p[(r0 + 8) * 68 + idx] = pkh(sspf(a1[j][2] * INV32 + bb0),
                                               sspf(a1[j][3] * INV32 + bb1));
            }
        }
        // pair barrier: warps wm and wm+8 both write slab wm; GEMM2 reads all cols
        asm volatile("bar.sync %0, %1;" :: "r"(wm + 1), "r"(64) : "memory");
        // prefetch tile T+1 into registers
        float2 pf[7]; int pa = -1, pn = 0;
        if (T + 1 < ntile) {
#pragma unroll
            for (int k = 0; k < 7; ++k) {
                int idx = tid + k * 512;
                if (idx < 3200) {
                    int rr = idx / 25, pr = idx - rr * 25;
                    uint32_t u = list[(T + 1) * 128 + rr];
                    size_t gr = (u == 0xFFFFFFFFu) ? 0 : (size_t)u;
                    pf[k] = *(const float2*)(fij + gr * 50 + 2 * pr);
                }
            }
            if (tid < 128) {
                uint32_t u = list[(T + 1) * 128 + tid];
                if (u != 0xFFFFFFFFu) { pa = (int)(u >> 6); pn = nbrs[u]; }
            }
        }
        // GEMM2 (K=128)
        float a2[8][4]{};
#pragma unroll
        for (int ks = 0; ks < 8; ++ks)
            psf8(w1p, 68, wm * 16, ks * 8, b2f + (ks * 16 + wn * 8) * 32, lane, a2);
        // epi2: (d*INV32 + b2) * y[nb] -> pw
        {
            int r0 = wm * 16 + g, r1 = r0 + 8;
            int aA = ats_t[buf * 128 + r0], aB = ats_t[buf * 128 + r1];
            size_t yi0 = (aA >= 0) ? ((size_t)(aA >> 10) * 1024 + nbs_t[buf * 128 + r0]) : 0;
            size_t yi1 = (aB >= 0) ? ((size_t)(aB >> 10) * 1024 + nbs_t[buf * 128 + r1]) : 0;
            const float* y0 = Y + yi0 * 128;
            const float* y1 = Y + yi1 * 128;
#pragma unroll
            for (int j = 0; j < 8; ++j) {
                int c = wn * 64 + j * 8 + 2 * t;
                float2 ya = *(const float2*)(y0 + c);
                float2 yc = *(const float2*)(y1 + c);
                float bb0 = b2s[c], bb1 = b2s[c + 1];
                *(float2*)(pw + r0 * 132 + c) =
                    make_float2((a2[j][0] * INV32 + bb0) * ya.x, (a2[j][1] * INV32 + bb1) * ya.y);
                *(float2*)(pw + r1 * 132 + c) =
                    make_float2((a2[j][2] * INV32 + bb0) * yc.x, (a2[j][3] * INV32 + bb1) * yc.y);
            }
        }
        __syncthreads();    // #1: pw visible; fjs reads done
        // drain prefetch: fjs[T+1] + meta[buf^1]
        if (T + 1 < ntile) {
#pragma unroll
            for (int k = 0; k < 7; ++k) {
                int idx = tid + k * 512;
                if (idx < 3200) {
                    int rr = idx / 25, pr = idx - rr * 25;
                    int q = pr & 7;
                    fjs[rr * 36 + (pr >> 3) * 8 + (q & 3) * 2 + (q >> 2)] = pkh(pf[k].x, pf[k].y);
                }
            }
            if (tid < 128) { ats_t[(buf ^ 1) * 128 + tid] = pa; nbs_t[(buf ^ 1) * 128 + tid] = pn; }
        }
        // segmented reduce -> atomicAdd V
        {
            int f = tid & 127, q = tid >> 7;
            float s = 0.f; int cur = ats_t[buf * 128 + q * 32];
            for (int r = q * 32; r < q * 32 + 32; ++r) {
                int a = ats_t[buf * 128 + r];
                if (a != cur) {
                    if (cur >= 0) atomicAdd(V + (size_t)cur * 128 + f, s);
                    s = 0.f; cur = a;
                }
                s += pw[r * 132 + f];
            }
            if (cur >= 0) atomicAdd(V + (size_t)cur * 128 + f, s);
        }
        __syncthreads();    // #2
    }
}

extern "C" void kernel_launch(void* const* d_in, const int* in_sizes, int n_in,
                              void* d_out, int out_size) {
    const float* x      = (const float*)d_in[0];
    const float* rij    = (const float*)d_in[1];
    const int*   nbrs   = (const int*)d_in[2];
    const float* nmask  = (const float*)d_in[3];
    const float* fij    = (const float*)d_in[4];
    const float* Win2f  = (const float*)d_in[5];
    const float* Wf1    = (const float*)d_in[6];
    const float* bf1    = (const float*)d_in[7];
    const float* Wf2    = (const float*)d_in[8];
    const float* bf2    = (const float*)d_in[9];
    const float* Wfout  = (const float*)d_in[10];
    const float* bfout  = (const float*)d_in[11];
    const float* Wdense = (const float*)d_in[12];
    const float* bdense = (const float*)d_in[13];
    float* out = (float*)d_out;

    cudaFuncSetAttribute(gemmB,  cudaFuncAttributeMaxDynamicSharedMemorySize, 100352);
    cudaFuncSetAttribute(gemmC,  cudaFuncAttributeMaxDynamicSharedMemorySize, 202752);
    cudaFuncSetAttribute(main12, cudaFuncAttributeMaxDynamicSharedMemorySize, 222464);

    void *py, *pv, *p0, *p1, *p2, *p3, *p4, *pl;
    cudaGetSymbolAddress(&py, g_y);
    cudaGetSymbolAddress(&pv, g_v);
    cudaGetSymbolAddress(&p0, g_wp0);
    cudaGetSymbolAddress(&p1, g_wp1);
    cudaGetSymbolAddress(&p2, g_wp2);
    cudaGetSymbolAddress(&p3, g_wp3);
    cudaGetSymbolAddress(&p4, g_wp4);
    cudaGetSymbolAddress(&pl, g_list);

    pack5<<<576, 32>>>(Win2f, Wf1, Wf2, Wfout, Wdense,
                       (float4*)p0, (float4*)p1, (float4*)p2, (float4*)p3, (float4*)p4);
    gemmB<<<128, 512, 100352>>>(x, (const float4*)p0, (float*)py, (float4*)pv);
    main12<<<148, 512, 222464>>>(fij, rij, nbrs, nmask, bf1, bf2,
                                 (const float4*)p1, (const float4*)p2,
                                 (const float*)py, (float*)pv, (uint32_t*)pl);
    gemmC<<<128, 512, 202752>>>((const float*)pv, (const float4*)p3, (const float4*)p4,
                                bfout, bdense, out);
}